// round 14
// baseline (speedup 1.0000x reference)
#include <cuda_runtime.h>
#include <math.h>

#define B 4
#define N 512
#define HID 100
#define HP 128
#define OUTF 6
#define FULL 0xFFFFFFFFu
#define NBLK (B * HID)       // 400 column blocks
#define EBLK 128             // epilogue blocks (16 rows each -> 2048 rows)

// Scratch (static device; no allocation anywhere)
__device__ float g_S[B * N * HP];
__device__ int   g_done  = 0;
__device__ int   g_done2 = 0;

__device__ __forceinline__ float softplus_f(float v)
{
    return fmaxf(v, 0.f) + log1pf(expf(-fabsf(v)));
}

// ---------------------------------------------------------------------------
// Single fused kernel.
// Phase 1 (all 400 blocks): one (b,k) column each, 512 threads (thread = j).
//   P,Q from inp row + W1 col; hybrid bitonic sort (shfl <32, smem >=32);
//   warp-shuffle scan; binary search -> closed-form T -> S -> g_S.
// Phase 2 (blocks 0..127): spin until all columns published, then row-GEMV
//   epilogue (warp per row) + softplus combine -> out.
// ---------------------------------------------------------------------------
__global__ __launch_bounds__(512) void kAB(
    const float* __restrict__ inp, const float* __restrict__ W1,
    const float* __restrict__ b1,  const float* __restrict__ W2,
    const float* __restrict__ b2,  float* __restrict__ out)
{
    int b    = blockIdx.x / HID;
    int k    = blockIdx.x - b * HID;
    int tid  = threadIdx.x;
    int lane = tid & 31;
    int wid  = tid >> 5;

    __shared__ float Qs[N];
    __shared__ float Cs[N];
    __shared__ float wsum[16];
    __shared__ float xch[N];

    // node features for row tid
    const float* e = inp + (b * N + tid) * 6;
    float y = e[0], x = e[1], tau = e[2], sig = e[3], c = e[4], d = e[5];

    // W1 column k (uniform across block)
    float w0 = W1[0*HID+k], w1 = W1[1*HID+k], w2 = W1[2*HID+k], w3 = W1[3*HID+k];
    float w4 = W1[4*HID+k], w5 = W1[5*HID+k], w6 = W1[6*HID+k], w7 = W1[7*HID+k];
    float w8 = W1[8*HID+k], w9 = W1[9*HID+k], bk = b1[k];

    float P = tau*w0 + sig*w1 + c*w2 + d*w3 + y*w8 + x*w9 + bk;
    float Q = tau*w4 + sig*w5 + c*w6 + d*w7 - y*w8 - x*w9;

    // ---- bitonic sort (ascending across tid), value in register
    float v = Q;
    #pragma unroll
    for (int size = 2; size <= N; size <<= 1) {
        bool dirAsc = ((tid & size) == 0);
        #pragma unroll
        for (int stride = size >> 1; stride > 0; stride >>= 1) {
            float pv;
            if (stride >= 32) {
                xch[tid] = v;
                __syncthreads();
                pv = xch[tid ^ stride];
                __syncthreads();
            } else {
                pv = __shfl_xor_sync(FULL, v, stride);
            }
            bool lower = ((tid & stride) == 0);
            v = (lower == dirAsc) ? fminf(v, pv) : fmaxf(v, pv);
        }
    }
    Qs[tid] = v;

    // ---- inclusive scan: warp shfl scan + warp-sum scan
    float s = v;
    #pragma unroll
    for (int off = 1; off < 32; off <<= 1) {
        float t = __shfl_up_sync(FULL, s, off);
        if (lane >= off) s += t;
    }
    if (lane == 31) wsum[wid] = s;
    __syncthreads();
    if (wid == 0) {
        float ws = (lane < 16) ? wsum[lane] : 0.f;
        #pragma unroll
        for (int off = 1; off < 16; off <<= 1) {
            float t = __shfl_up_sync(FULL, ws, off);
            if (lane >= off) ws += t;
        }
        if (lane < 16) wsum[lane] = ws;
    }
    __syncthreads();
    float base = (wid == 0) ? 0.f : wsum[wid - 1];
    float inc  = base + s;
    Cs[tid] = inc;
    float SQ = wsum[15];
    __syncthreads();

    // ---- binary search: m = #{Qs < -P}
    float key = -P;
    int lo = 0, hi = N;
    #pragma unroll
    for (int it = 0; it < 9; it++) {
        int mid = (lo + hi) >> 1;
        bool lt = Qs[mid] < key;
        lo = lt ? mid + 1 : lo;
        hi = lt ? hi : mid;
    }
    float Cm = (lo == 0) ? 0.f : Cs[lo - 1];
    float T  = (float)(N - 2 * lo) * P + SQ - 2.f * Cm;

    float S = 0.55f * ((float)(N - 1) * P + SQ - Q)
            + 0.45f * (T - fabsf(P + Q));
    g_S[(b * N + tid) * HP + k] = S;

    // ---- publish this column (release)
    __syncthreads();
    if (tid == 0) {
        __threadfence();
        atomicAdd(&g_done, 1);
    }

    if (blockIdx.x >= EBLK) return;

    // ---- wait for all columns (acquire)
    if (tid == 0) {
        volatile int* dp = &g_done;
        while (*dp < NBLK) { __nanosleep(64); }
        __threadfence();
    }
    __syncthreads();

    // ---- epilogue: warp per row; this block covers 16 rows
    {
        int row = blockIdx.x * 16 + wid;     // b*N + i, 0..2047
        const float* Sr = g_S + row * HP;

        float par[OUTF];
        #pragma unroll
        for (int o = 0; o < OUTF; o++) par[o] = 0.f;

        #pragma unroll
        for (int cc = 0; cc < 4; cc++) {
            int kc = lane + 32 * cc;
            if (kc < HID) {
                float sv = Sr[kc];
                #pragma unroll
                for (int o = 0; o < OUTF; o++)
                    par[o] += sv * W2[kc * OUTF + o];
            }
        }
        #pragma unroll
        for (int off = 16; off > 0; off >>= 1)
            #pragma unroll
            for (int o = 0; o < OUTF; o++)
                par[o] += __shfl_down_sync(FULL, par[o], off);

        if (lane == 0) {
            const float* ei = inp + row * 6;
            float* ot = out + row * 6;
            float p0 = par[0] + (float)(N - 1) * b2[0];
            float p1 = par[1] + (float)(N - 1) * b2[1];
            float p2 = par[2] + (float)(N - 1) * b2[2];
            float p3 = par[3] + (float)(N - 1) * b2[3];
            float p4 = par[4] + (float)(N - 1) * b2[4];
            float p5 = par[5] + (float)(N - 1) * b2[5];
            ot[0] = ei[0] + 0.1f * p0;
            ot[1] = ei[1] + 0.1f * p1;
            ot[2] = ei[2] + 0.1f * p2;
            ot[3] = ei[3] + 0.1f * p3;
            ot[4] = 0.1f * softplus_f(p4);
            ot[5] = 0.1f * softplus_f(p5);
        }
    }

    // ---- self-reset counters for the next (graph-replayed) launch
    __syncthreads();
    if (tid == 0) {
        int old = atomicAdd(&g_done2, 1);
        if (old == EBLK - 1) {
            g_done  = 0;
            g_done2 = 0;
            __threadfence();
        }
    }
}

// ---------------------------------------------------------------------------
extern "C" void kernel_launch(void* const* d_in, const int* in_sizes, int n_in,
                              void* d_out, int out_size)
{
    const float* inp = (const float*)d_in[0];
    const float* W1  = (const float*)d_in[1];
    const float* b1  = (const float*)d_in[2];
    const float* W2  = (const float*)d_in[3];
    const float* b2  = (const float*)d_in[4];
    float* out = (float*)d_out;

    kAB<<<NBLK, 512>>>(inp, W1, b1, W2, b2, out);
}